// round 1
// baseline (speedup 1.0000x reference)
#include <cuda_runtime.h>

// ---------------------------------------------------------------------------
// involution_81106162418291
// B=4, C=256, H=W=56, GC=4 -> G=64, K=7 -> K2=49, Cr=64, stride=1, pad=3
// Inputs: x(4,256,56,56) w1(64,256) b1(64) gamma(64) beta(64) mean(64) var(64)
//         w2(3136,64) b2(3136)   Output: (4,256,56,56) fp32
// ---------------------------------------------------------------------------

#define Bsz 4
#define C   256
#define Cr  64
#define HW  3136     // 56*56
#define Hdim 56
#define G   64
#define K2  49

__device__ float g_y[Bsz * Cr * HW];   // scratch: relu(bn(conv1(x)))

// ---------------------------------------------------------------------------
// Kernel 1: y[b,cr,hw] = relu( (sum_c w1[cr,c]*x[b,c,hw] + b1)*inv + shift )
// grid (49, 4): blockIdx.x -> 256-pixel chunk, blockIdx.y -> 16-channel split
// ---------------------------------------------------------------------------
__global__ void __launch_bounds__(256) k1_conv_bn_relu(
    const float* __restrict__ x,  const float* __restrict__ w1,
    const float* __restrict__ b1, const float* __restrict__ gamma,
    const float* __restrict__ beta, const float* __restrict__ mean,
    const float* __restrict__ var)
{
    __shared__ float w1s[C * 17];            // [c][cr] padded (17) -> conflict-free
    const int tid = threadIdx.x;
    const int cr0 = blockIdx.y * 16;

    for (int idx = tid; idx < 16 * C; idx += 256) {
        int cr = idx >> 8;                   // 0..15
        int c  = idx & 255;
        w1s[c * 17 + cr] = w1[(cr0 + cr) * C + c];
    }
    __syncthreads();

    const int p  = blockIdx.x * 256 + tid;   // global pixel 0..12543
    const int b  = p / HW;
    const int hw = p - b * HW;
    const float* xb = x + (size_t)b * C * HW + hw;

    float acc[16];
#pragma unroll
    for (int i = 0; i < 16; i++) acc[i] = 0.f;

#pragma unroll 4
    for (int c = 0; c < C; c++) {
        float xv = xb[c * HW];
#pragma unroll
        for (int i = 0; i < 16; i++) acc[i] += w1s[c * 17 + i] * xv;
    }

#pragma unroll
    for (int i = 0; i < 16; i++) {
        int cr = cr0 + i;
        float inv   = gamma[cr] * rsqrtf(var[cr] + 1e-5f);
        float shift = beta[cr] - mean[cr] * inv;
        float v = (acc[i] + b1[cr]) * inv + shift;
        g_y[(b * Cr + cr) * HW + hw] = fmaxf(v, 0.f);
    }
}

// ---------------------------------------------------------------------------
// Kernel 2 (fused): per 8x8 pixel tile, for each group g:
//   weight[k,pix] = sum_cr w2[g*49+k, cr] * y[cr,pix] + b2   (4x4 reg-tiled GEMM)
//   out[g*4+c, pix] = sum_{7x7} weight[k,pix] * x[g*4+c, pix+offset]
// grid (49, 4): blockIdx.x -> (th,tw) in 7x7 tiles, blockIdx.y -> batch
// ---------------------------------------------------------------------------
__global__ void __launch_bounds__(256) k2_involution(
    const float* __restrict__ x, const float* __restrict__ w2,
    const float* __restrict__ b2, float* __restrict__ out)
{
    __shared__ float ys [Cr * 64];       // [cr][pix]           16.0 KB
    __shared__ float w2s[32 * 68];       // [cr][k padded 68]    8.7 KB
    __shared__ float wts[K2 * 64];       // [k][pix]            12.5 KB
    __shared__ float xs [4 * 14 * 16];   // [c][row][col16]      3.5 KB

    const int tid = threadIdx.x;
    const int b   = blockIdx.y;
    const int th  = blockIdx.x / 7;
    const int tw  = blockIdx.x - th * 7;
    const int h0  = th * 8, w0 = tw * 8;

    // load y tile (reused by all 64 groups)
    for (int idx = tid; idx < Cr * 64; idx += 256) {
        int cr = idx >> 6, pix = idx & 63;
        int ph = pix >> 3, pw = pix & 7;
        ys[idx] = g_y[(b * Cr + cr) * HW + (h0 + ph) * Hdim + (w0 + pw)];
    }

    // GEMM register-tile coords: 4 k-rows x 4 pix-cols per thread
    const int k0 = (tid >> 4) * 4;       // 0..60 (k padded to 64)
    const int p0 = (tid & 15) * 4;       // 0..60
    // involution coords: channel-in-group x pixel
    const int ci   = tid >> 6;           // 0..3
    const int pixi = tid & 63;
    const int phi  = pixi >> 3, pwi = pixi & 7;

    for (int g = 0; g < G; g++) {
        float4 a0 = {0,0,0,0}, a1 = {0,0,0,0}, a2 = {0,0,0,0}, a3 = {0,0,0,0};

#pragma unroll
        for (int ch = 0; ch < 2; ch++) {
            const int cr0 = ch * 32;
            __syncthreads();   // also guards prev group's wts/xs consumption
            // stage w2 chunk, transposed: w2s[cr][k]
            for (int idx = tid; idx < K2 * 32; idx += 256) {
                int k = idx >> 5, cr = idx & 31;
                w2s[cr * 68 + k] = w2[(g * K2 + k) * Cr + cr0 + cr];
            }
            if (ch == 0) {
                // stage x halo tile for this group's 4 channels
                for (int idx = tid; idx < 4 * 14 * 14; idx += 256) {
                    int c   = idx / 196;
                    int rem = idx - c * 196;
                    int r   = rem / 14;
                    int col = rem - r * 14;
                    int hh = h0 + r - 3, ww = w0 + col - 3;
                    float v = 0.f;
                    if (hh >= 0 && hh < Hdim && ww >= 0 && ww < Hdim)
                        v = x[((size_t)(b * C + g * 4 + c) * Hdim + hh) * Hdim + ww];
                    xs[(c * 14 + r) * 16 + col] = v;
                }
            }
            __syncthreads();

#pragma unroll
            for (int cr = 0; cr < 32; cr++) {
                float4 av = *(const float4*)&w2s[cr * 68 + k0];
                float4 bv = *(const float4*)&ys[(cr0 + cr) * 64 + p0];
                a0.x += av.x * bv.x; a0.y += av.x * bv.y; a0.z += av.x * bv.z; a0.w += av.x * bv.w;
                a1.x += av.y * bv.x; a1.y += av.y * bv.y; a1.z += av.y * bv.z; a1.w += av.y * bv.w;
                a2.x += av.z * bv.x; a2.y += av.z * bv.y; a2.z += av.z * bv.z; a2.w += av.z * bv.w;
                a3.x += av.w * bv.x; a3.y += av.w * bv.y; a3.z += av.w * bv.z; a3.w += av.w * bv.w;
            }
        }

        // add bias, scatter weights to smem (only valid k < 49)
        float4 accs[4] = {a0, a1, a2, a3};
#pragma unroll
        for (int i = 0; i < 4; i++) {
            int k = k0 + i;
            if (k < K2) {
                float bias = b2[g * K2 + k];
                float* w = &wts[k * 64 + p0];
                w[0] = accs[i].x + bias;
                w[1] = accs[i].y + bias;
                w[2] = accs[i].z + bias;
                w[3] = accs[i].w + bias;
            }
        }
        __syncthreads();

        // involution MAC: 7x7 dynamic kernel
        float s = 0.f;
#pragma unroll
        for (int ky = 0; ky < 7; ky++) {
#pragma unroll
            for (int kx = 0; kx < 7; kx++) {
                s += wts[(ky * 7 + kx) * 64 + pixi]
                   * xs[(ci * 14 + phi + ky) * 16 + pwi + kx];
            }
        }
        out[((size_t)(b * C + g * 4 + ci) * Hdim + h0 + phi) * Hdim + (w0 + pwi)] = s;
    }
}

extern "C" void kernel_launch(void* const* d_in, const int* in_sizes, int n_in,
                              void* d_out, int out_size)
{
    const float* x     = (const float*)d_in[0];
    const float* w1    = (const float*)d_in[1];
    const float* b1    = (const float*)d_in[2];
    const float* gamma = (const float*)d_in[3];
    const float* beta  = (const float*)d_in[4];
    const float* mean  = (const float*)d_in[5];
    const float* var   = (const float*)d_in[6];
    const float* w2    = (const float*)d_in[7];
    const float* b2    = (const float*)d_in[8];
    float* out = (float*)d_out;

    dim3 g1(49, 4);   // 12544 pixels / 256, 4 channel-splits of 16
    k1_conv_bn_relu<<<g1, 256>>>(x, w1, b1, gamma, beta, mean, var);

    dim3 g2(49, 4);   // 7x7 pixel tiles, 4 batches
    k2_involution<<<g2, 256>>>(x, w2, b2, out);
}

// round 2
// speedup vs baseline: 1.3897x; 1.3897x over previous
#include <cuda_runtime.h>

// ---------------------------------------------------------------------------
// involution_81106162418291
// B=4, C=256, H=W=56, GC=4 -> G=64, K=7 -> K2=49, Cr=64, stride=1, pad=3
// ---------------------------------------------------------------------------

#define Bsz 4
#define C   256
#define Cr  64
#define HW  3136     // 56*56
#define Hdim 56
#define G   64
#define K2  49

__device__ float g_y[Bsz * Cr * HW];   // scratch: relu(bn(conv1(x)))

// ---------------------------------------------------------------------------
// Kernel 1: y[b,cr,hw] = relu( (sum_c w1[cr,c]*x[b,c,hw] + b1)*inv + shift )
// grid (49, 8): blockIdx.x -> 256-pixel chunk, blockIdx.y -> 8-channel split
// ---------------------------------------------------------------------------
__global__ void __launch_bounds__(256) k1_conv_bn_relu(
    const float* __restrict__ x,  const float* __restrict__ w1,
    const float* __restrict__ b1, const float* __restrict__ gamma,
    const float* __restrict__ beta, const float* __restrict__ mean,
    const float* __restrict__ var)
{
    __shared__ float w1s[C * 9];             // [c][cr] padded (9) -> conflict-free
    const int tid = threadIdx.x;
    const int cr0 = blockIdx.y * 8;

    for (int idx = tid; idx < 8 * C; idx += 256) {
        int cr = idx >> 8;                   // 0..7
        int c  = idx & 255;
        w1s[c * 9 + cr] = w1[(cr0 + cr) * C + c];
    }
    __syncthreads();

    const int p  = blockIdx.x * 256 + tid;   // global pixel 0..12543
    const int b  = p / HW;
    const int hw = p - b * HW;
    const float* xb = x + (size_t)b * C * HW + hw;

    float acc[8];
#pragma unroll
    for (int i = 0; i < 8; i++) acc[i] = 0.f;

#pragma unroll 4
    for (int c = 0; c < C; c++) {
        float xv = xb[c * HW];
#pragma unroll
        for (int i = 0; i < 8; i++) acc[i] += w1s[c * 9 + i] * xv;
    }

#pragma unroll
    for (int i = 0; i < 8; i++) {
        int cr = cr0 + i;
        float inv   = gamma[cr] * rsqrtf(var[cr] + 1e-5f);
        float shift = beta[cr] - mean[cr] * inv;
        float v = (acc[i] + b1[cr]) * inv + shift;
        g_y[(b * Cr + cr) * HW + hw] = fmaxf(v, 0.f);
    }
}

// ---------------------------------------------------------------------------
// Kernel 2 (fused): block = (8x8 pixel tile, batch, group).  grid (49, 4, 64).
//   weight[k,pix] = sum_cr w2[g*49+k, cr] * y[cr,pix] + b2   (4x4 reg-tiled)
//   out[g*4+c,pix] = sum_{7x7} weight[k,pix] * x[g*4+c, pix+off]
// Only 2 __syncthreads per block; 12544 blocks keep all SMs busy.
// ---------------------------------------------------------------------------
__global__ void __launch_bounds__(256) k2_involution(
    const float* __restrict__ x, const float* __restrict__ w2,
    const float* __restrict__ b2, float* __restrict__ out)
{
    __shared__ float ys [Cr * 64];       // [cr][pix]            16.0 KB
    __shared__ float w2s[Cr * 64];       // [cr][k padded to 64] 16.0 KB
    __shared__ float wts[K2 * 64];       // [k][pix]             12.5 KB
    __shared__ float xs [4 * 14 * 16];   // [c][row][col16]       3.5 KB

    const int tid = threadIdx.x;
    const int b   = blockIdx.y;
    const int g   = blockIdx.z;
    const int th  = blockIdx.x / 7;
    const int tw  = blockIdx.x - th * 7;
    const int h0  = th * 8, w0 = tw * 8;

    // ---- stage y tile (64 cr x 64 pix) ----
    for (int idx = tid; idx < Cr * 64; idx += 256) {
        int cr = idx >> 6, pix = idx & 63;
        int ph = pix >> 3, pw = pix & 7;
        ys[idx] = g_y[(b * Cr + cr) * HW + (h0 + ph) * Hdim + (w0 + pw)];
    }
    // ---- stage w2 rows for this group, transposed: w2s[cr][k] ----
    for (int idx = tid; idx < K2 * Cr; idx += 256) {
        int k = idx >> 6, cr = idx & 63;                 // cr fast -> coalesced gmem
        w2s[cr * 64 + k] = w2[(g * K2 + k) * Cr + cr];
    }
    // ---- stage x halo tile (4 channels, 14x14, row pitch 16) ----
    for (int idx = tid; idx < 4 * 14 * 14; idx += 256) {
        int c   = idx / 196;
        int rem = idx - c * 196;
        int r   = rem / 14;
        int col = rem - r * 14;
        int hh = h0 + r - 3, ww = w0 + col - 3;
        float v = 0.f;
        if (hh >= 0 && hh < Hdim && ww >= 0 && ww < Hdim)
            v = x[((size_t)(b * C + g * 4 + c) * Hdim + hh) * Hdim + ww];
        xs[(c * 14 + r) * 16 + col] = v;
    }
    __syncthreads();

    // ---- GEMM: 4 k-rows x 4 pix-cols per thread (k padded 49->64) ----
    const int k0 = (tid >> 4) * 4;       // 0..60
    const int p0 = (tid & 15) * 4;       // 0..60

    float4 a0 = {0,0,0,0}, a1 = {0,0,0,0}, a2 = {0,0,0,0}, a3 = {0,0,0,0};
#pragma unroll
    for (int cr = 0; cr < Cr; cr++) {
        float4 av = *(const float4*)&w2s[cr * 64 + k0];   // broadcast (16 lanes)
        float4 bv = *(const float4*)&ys[cr * 64 + p0];
        a0.x += av.x * bv.x; a0.y += av.x * bv.y; a0.z += av.x * bv.z; a0.w += av.x * bv.w;
        a1.x += av.y * bv.x; a1.y += av.y * bv.y; a1.z += av.y * bv.z; a1.w += av.y * bv.w;
        a2.x += av.z * bv.x; a2.y += av.z * bv.y; a2.z += av.z * bv.z; a2.w += av.z * bv.w;
        a3.x += av.w * bv.x; a3.y += av.w * bv.y; a3.z += av.w * bv.z; a3.w += av.w * bv.w;
    }

    // ---- bias add + scatter valid k rows to smem ----
    float4 accs[4] = {a0, a1, a2, a3};
#pragma unroll
    for (int i = 0; i < 4; i++) {
        int k = k0 + i;
        if (k < K2) {
            float bias = b2[g * K2 + k];
            float* w = &wts[k * 64 + p0];
            w[0] = accs[i].x + bias;
            w[1] = accs[i].y + bias;
            w[2] = accs[i].z + bias;
            w[3] = accs[i].w + bias;
        }
    }
    __syncthreads();

    // ---- involution: 7x7 dynamic kernel MAC ----
    const int ci   = tid >> 6;           // 0..3 channel-in-group
    const int pixi = tid & 63;
    const int phi  = pixi >> 3, pwi = pixi & 7;

    float s = 0.f;
#pragma unroll
    for (int ky = 0; ky < 7; ky++) {
#pragma unroll
        for (int kx = 0; kx < 7; kx++) {
            s += wts[(ky * 7 + kx) * 64 + pixi]
               * xs[(ci * 14 + phi + ky) * 16 + pwi + kx];
        }
    }
    out[((size_t)(b * C + g * 4 + ci) * Hdim + h0 + phi) * Hdim + (w0 + pwi)] = s;
}

extern "C" void kernel_launch(void* const* d_in, const int* in_sizes, int n_in,
                              void* d_out, int out_size)
{
    const float* x     = (const float*)d_in[0];
    const float* w1    = (const float*)d_in[1];
    const float* b1    = (const float*)d_in[2];
    const float* gamma = (const float*)d_in[3];
    const float* beta  = (const float*)d_in[4];
    const float* mean  = (const float*)d_in[5];
    const float* var   = (const float*)d_in[6];
    const float* w2    = (const float*)d_in[7];
    const float* b2    = (const float*)d_in[8];
    float* out = (float*)d_out;

    dim3 g1(49, 8);
    k1_conv_bn_relu<<<g1, 256>>>(x, w1, b1, gamma, beta, mean, var);

    dim3 g2(49, 4, 64);   // pixel tiles x batch x groups
    k2_involution<<<g2, 256>>>(x, w2, b2, out);
}

// round 4
// speedup vs baseline: 3.2557x; 2.3427x over previous
#include <cuda_runtime.h>
#include <cuda_bf16.h>
#include <cstdint>

// ---------------------------------------------------------------------------
// involution_81106162418291  (mma.sync bf16 hi/lo version — compute_103-safe)
// B=4, C=256, H=W=56, GC=4 -> G=64, K=7 -> K2=49, Cr=64, stride=1, pad=3
// ---------------------------------------------------------------------------

#define Bsz 4
#define C    256
#define Cr   64
#define HW   3136
#define Hdim 56
#define G    64
#define K2   49

__device__ __nv_bfloat16 g_yhi[Bsz * HW * Cr];     // y hi, layout [b][hw][cr]
__device__ __nv_bfloat16 g_ylo[Bsz * HW * Cr];
__device__ __nv_bfloat16 g_w2hi[K2 * G * Cr];      // w2 hi, layout [row][cr]
__device__ __nv_bfloat16 g_w2lo[K2 * G * Cr];

__device__ __forceinline__ uint32_t smem_u32(const void* p) {
    uint32_t a;
    asm("{ .reg .u64 t; cvta.to.shared.u64 t, %1; cvt.u32.u64 %0, t; }"
        : "=r"(a) : "l"(p));
    return a;
}

#define LDSM_X4(r0,r1,r2,r3,addr) \
    asm volatile("ldmatrix.sync.aligned.m8n8.x4.shared.b16 {%0,%1,%2,%3}, [%4];" \
        : "=r"(r0),"=r"(r1),"=r"(r2),"=r"(r3) : "r"(addr))
#define LDSM_X2(r0,r1,addr) \
    asm volatile("ldmatrix.sync.aligned.m8n8.x2.shared.b16 {%0,%1}, [%2];" \
        : "=r"(r0),"=r"(r1) : "r"(addr))
#define MMA16816(c,a,b) \
    asm volatile("mma.sync.aligned.m16n8k16.row.col.f32.bf16.bf16.f32 " \
        "{%0,%1,%2,%3}, {%4,%5,%6,%7}, {%8,%9}, {%0,%1,%2,%3};" \
        : "+f"((c)[0]),"+f"((c)[1]),"+f"((c)[2]),"+f"((c)[3]) \
        : "r"((a)[0]),"r"((a)[1]),"r"((a)[2]),"r"((a)[3]), "r"((b)[0]),"r"((b)[1]))

// ---------------------------------------------------------------------------
// k0: split w2 into bf16 hi/lo. grid 784 x 256 covers 49*64*64 = 200704.
// ---------------------------------------------------------------------------
__global__ void __launch_bounds__(256) k0_w2split(const float* __restrict__ w2) {
    int i = blockIdx.x * 256 + threadIdx.x;
    float v = w2[i];
    __nv_bfloat16 h = __float2bfloat16(v);
    g_w2hi[i] = h;
    g_w2lo[i] = __float2bfloat16(v - __bfloat162float(h));
}

// ---------------------------------------------------------------------------
// k1: y = relu(bn(conv1(x))), bf16 hi/lo at [b][hw][cr]
// ---------------------------------------------------------------------------
__global__ void __launch_bounds__(256) k1_conv_bn_relu(
    const float* __restrict__ x,  const float* __restrict__ w1,
    const float* __restrict__ b1, const float* __restrict__ gamma,
    const float* __restrict__ beta, const float* __restrict__ mean,
    const float* __restrict__ var)
{
    __shared__ float w1s[C * 9];
    const int tid = threadIdx.x;
    const int cr0 = blockIdx.y * 8;

    for (int idx = tid; idx < 8 * C; idx += 256) {
        int cr = idx >> 8;
        int c  = idx & 255;
        w1s[c * 9 + cr] = w1[(cr0 + cr) * C + c];
    }
    __syncthreads();

    const int p  = blockIdx.x * 256 + tid;
    const int b  = p / HW;
    const int hw = p - b * HW;
    const float* xb = x + (size_t)b * C * HW + hw;

    float acc[8];
#pragma unroll
    for (int i = 0; i < 8; i++) acc[i] = 0.f;

#pragma unroll 4
    for (int c = 0; c < C; c++) {
        float xv = xb[c * HW];
#pragma unroll
        for (int i = 0; i < 8; i++) acc[i] += w1s[c * 9 + i] * xv;
    }

#pragma unroll
    for (int i = 0; i < 8; i++) {
        int cr = cr0 + i;
        float inv   = gamma[cr] * rsqrtf(var[cr] + 1e-5f);
        float shift = beta[cr] - mean[cr] * inv;
        float v = fmaxf((acc[i] + b1[cr]) * inv + shift, 0.f);
        __nv_bfloat16 h = __float2bfloat16(v);
        size_t o = (size_t)(b * HW + hw) * Cr + cr;
        g_yhi[o] = h;
        g_ylo[o] = __float2bfloat16(v - __bfloat162float(h));
    }
}

// ---------------------------------------------------------------------------
// k2: block = (8x8 pixel tile, batch, group). grid (49, 4, 64), 128 threads.
//   GEMM D[64k x 64px] = w2_g[64 x 64cr] * y_tile^T  via mma.sync bf16 (3-pass)
//   Warp w owns pixel slab [16w, 16w+16). Then wts -> smem -> 7x7 involution.
// smem map (36864B): Ahi@0 Alo@9216 Bhi@18432 Blo@27648, rows of 72 bf16 (144B)
//   after GEMM: wts(49x65 f32)@0, xs(4x14x16 f32)@12752  (overlays A, dead)
// ---------------------------------------------------------------------------
#define S_AHI 0u
#define S_ALO 9216u
#define S_BHI 18432u
#define S_BLO 27648u
#define S_XS  12752u

__global__ void __launch_bounds__(128) k2_involution(
    const float* __restrict__ x, const float* __restrict__ b2,
    float* __restrict__ out)
{
    __shared__ __align__(16) char buf[36864];
    const uint32_t sb = smem_u32(buf);
    const int tid = threadIdx.x, wid = tid >> 5, lane = tid & 31;
    const int b  = blockIdx.y;
    const int g  = blockIdx.z;
    const int th = blockIdx.x / 7, tw = blockIdx.x - th * 7;
    const int h0 = th * 8, w0 = tw * 8;

    // ---- stage A (w2 hi/lo): 49 rows x 8 uint4 into 72-elem-stride rows ----
    const uint4* w2hi4 = (const uint4*)g_w2hi;
    const uint4* w2lo4 = (const uint4*)g_w2lo;
    for (int idx = tid; idx < K2 * 8; idx += 128) {
        int r = idx >> 3, j = idx & 7;
        int gidx = (g * K2 + r) * 8 + j;
        uint32_t off = (uint32_t)(r * 144 + j * 16);
        *(uint4*)(buf + S_AHI + off) = w2hi4[gidx];
        *(uint4*)(buf + S_ALO + off) = w2lo4[gidx];
    }
    // ---- stage B (y hi/lo): 64 pixel rows x 8 uint4 ----
    const uint4* yhi4 = (const uint4*)g_yhi;
    const uint4* ylo4 = (const uint4*)g_ylo;
    for (int idx = tid; idx < 64 * 8; idx += 128) {
        int n = idx >> 3, j = idx & 7;
        int hw = (h0 + (n >> 3)) * Hdim + w0 + (n & 7);
        int gidx = (b * HW + hw) * 8 + j;
        uint32_t off = (uint32_t)(n * 144 + j * 16);
        *(uint4*)(buf + S_BHI + off) = yhi4[gidx];
        *(uint4*)(buf + S_BLO + off) = ylo4[gidx];
    }
    __syncthreads();

    // ---- ldmatrix lane offsets ----
    // A (m16k16 x4): row = lane&15, col-half = lane>>4
    const uint32_t aoff = ((uint32_t)(lane & 15) * 72 + (uint32_t)(lane >> 4) * 8) * 2;
    // B (k16n8 x2): row n = lane&7, col-half = (lane>>3)&1
    const uint32_t boff = ((uint32_t)(wid * 16 + (lane & 7)) * 72
                         + (uint32_t)((lane >> 3) & 1) * 8) * 2;

    float c[4][2][4];
#pragma unroll
    for (int mt = 0; mt < 4; mt++)
#pragma unroll
        for (int nt = 0; nt < 2; nt++)
#pragma unroll
            for (int i = 0; i < 4; i++) c[mt][nt][i] = 0.f;

    // ---- pass group 1: A=hi, B=hi and B=lo ----
#pragma unroll
    for (int kk = 0; kk < 4; kk++) {
        uint32_t a[4][4], bh[2][2], bl[2][2];
#pragma unroll
        for (int mt = 0; mt < 4; mt++)
            LDSM_X4(a[mt][0], a[mt][1], a[mt][2], a[mt][3],
                    sb + S_AHI + aoff + (uint32_t)(mt * 16 * 144 + kk * 32));
#pragma unroll
        for (int nt = 0; nt < 2; nt++) {
            LDSM_X2(bh[nt][0], bh[nt][1],
                    sb + S_BHI + boff + (uint32_t)(nt * 8 * 144 + kk * 32));
            LDSM_X2(bl[nt][0], bl[nt][1],
                    sb + S_BLO + boff + (uint32_t)(nt * 8 * 144 + kk * 32));
        }
#pragma unroll
        for (int mt = 0; mt < 4; mt++)
#pragma unroll
            for (int nt = 0; nt < 2; nt++) {
                MMA16816(c[mt][nt], a[mt], bh[nt]);
                MMA16816(c[mt][nt], a[mt], bl[nt]);
            }
    }
    // ---- pass group 2: A=lo, B=hi ----
#pragma unroll
    for (int kk = 0; kk < 4; kk++) {
        uint32_t a[4][4], bh[2][2];
#pragma unroll
        for (int mt = 0; mt < 4; mt++)
            LDSM_X4(a[mt][0], a[mt][1], a[mt][2], a[mt][3],
                    sb + S_ALO + aoff + (uint32_t)(mt * 16 * 144 + kk * 32));
#pragma unroll
        for (int nt = 0; nt < 2; nt++)
            LDSM_X2(bh[nt][0], bh[nt][1],
                    sb + S_BHI + boff + (uint32_t)(nt * 8 * 144 + kk * 32));
#pragma unroll
        for (int mt = 0; mt < 4; mt++)
#pragma unroll
            for (int nt = 0; nt < 2; nt++)
                MMA16816(c[mt][nt], a[mt], bh[nt]);
    }
    __syncthreads();   // A/B regions now dead -> reuse as wts/xs

    float* wts = (float*)buf;               // [49][65]
    float* xs  = (float*)(buf + S_XS);      // [4][14][16]

    // ---- epilogue: c -> wts (+bias). row r = k index, col = pixel ----
#pragma unroll
    for (int mt = 0; mt < 4; mt++) {
        int r0 = mt * 16 + (lane >> 2);
        int r1 = r0 + 8;
        float bias0 = (r0 < K2) ? b2[g * K2 + r0] : 0.f;
        float bias1 = (r1 < K2) ? b2[g * K2 + r1] : 0.f;
#pragma unroll
        for (int nt = 0; nt < 2; nt++) {
            int col = wid * 16 + nt * 8 + (lane & 3) * 2;
            if (r0 < K2) {
                wts[r0 * 65 + col]     = c[mt][nt][0] + bias0;
                wts[r0 * 65 + col + 1] = c[mt][nt][1] + bias0;
            }
            if (r1 < K2) {
                wts[r1 * 65 + col]     = c[mt][nt][2] + bias1;
                wts[r1 * 65 + col + 1] = c[mt][nt][3] + bias1;
            }
        }
    }
    // ---- stage x halo (4 channels x 14x14, pitch 16) ----
    for (int idx = tid; idx < 4 * 196; idx += 128) {
        int ch = idx / 196, rem = idx - ch * 196;
        int r = rem / 14, col = rem - r * 14;
        int hh = h0 + r - 3, ww = w0 + col - 3;
        float v = 0.f;
        if (hh >= 0 && hh < Hdim && ww >= 0 && ww < Hdim)
            v = x[((size_t)(b * C + g * 4 + ch) * Hdim + hh) * Hdim + ww];
        xs[(ch * 14 + r) * 16 + col] = v;
    }
    __syncthreads();

    // ---- involution: thread = (pixel, ch-half); 2 channels per thread ----
    const int pixi = tid & 63;
    const int ch0  = tid >> 6;          // 0..1 -> channels ch0, ch0+2
    const int phi = pixi >> 3, pwi = pixi & 7;

    const float* x0 = xs + ((ch0)     * 14 + phi) * 16 + pwi;
    const float* x1 = xs + ((ch0 + 2) * 14 + phi) * 16 + pwi;
    float a0 = 0.f, a1 = 0.f;
#pragma unroll
    for (int ky = 0; ky < 7; ky++) {
#pragma unroll
        for (int kx = 0; kx < 7; kx++) {
            float wk = wts[(ky * 7 + kx) * 65 + pixi];
            a0 += wk * x0[ky * 16 + kx];
            a1 += wk * x1[ky * 16 + kx];
        }
    }
    size_t o0 = ((size_t)(b * C + g * 4 + ch0)     * Hdim + h0 + phi) * Hdim + w0 + pwi;
    size_t o1 = ((size_t)(b * C + g * 4 + ch0 + 2) * Hdim + h0 + phi) * Hdim + w0 + pwi;
    out[o0] = a0;
    out[o1] = a1;
}

extern "C" void kernel_launch(void* const* d_in, const int* in_sizes, int n_in,
                              void* d_out, int out_size)
{
    const float* x     = (const float*)d_in[0];
    const float* w1    = (const float*)d_in[1];
    const float* b1    = (const float*)d_in[2];
    const float* gamma = (const float*)d_in[3];
    const float* beta  = (const float*)d_in[4];
    const float* mean  = (const float*)d_in[5];
    const float* var   = (const float*)d_in[6];
    const float* w2    = (const float*)d_in[7];
    const float* b2    = (const float*)d_in[8];
    float* out = (float*)d_out;

    k0_w2split<<<784, 256>>>(w2);

    dim3 g1(49, 8);
    k1_conv_bn_relu<<<g1, 256>>>(x, w1, b1, gamma, beta, mean, var);

    dim3 g2(49, 4, 64);   // pixel tiles x batch x groups
    k2_involution<<<g2, 128>>>(x, b2, out);
}

// round 5
// speedup vs baseline: 3.3813x; 1.0386x over previous
#include <cuda_runtime.h>
#include <cuda_bf16.h>
#include <cstdint>

// ---------------------------------------------------------------------------
// involution_81106162418291  — row-strip persistent-A mma.sync bf16 hi/lo
// B=4, C=256, H=W=56, GC=4 -> G=64, K=7 -> K2=49, Cr=64, stride=1, pad=3
// ---------------------------------------------------------------------------

#define Bsz 4
#define C    256
#define Cr   64
#define HW   3136
#define Hdim 56
#define G    64
#define K2   49

__device__ __nv_bfloat16 g_yhi[Bsz * HW * Cr];     // y hi, [b][hw][cr]
__device__ __nv_bfloat16 g_ylo[Bsz * HW * Cr];
__device__ __nv_bfloat16 g_w2hi[K2 * G * Cr];      // w2 hi, [row][cr]
__device__ __nv_bfloat16 g_w2lo[K2 * G * Cr];

__device__ __forceinline__ uint32_t smem_u32(const void* p) {
    uint32_t a;
    asm("{ .reg .u64 t; cvta.to.shared.u64 t, %1; cvt.u32.u64 %0, t; }"
        : "=r"(a) : "l"(p));
    return a;
}

#define LDSM_X4(r0,r1,r2,r3,addr) \
    asm volatile("ldmatrix.sync.aligned.m8n8.x4.shared.b16 {%0,%1,%2,%3}, [%4];" \
        : "=r"(r0),"=r"(r1),"=r"(r2),"=r"(r3) : "r"(addr))
#define LDSM_X2(r0,r1,addr) \
    asm volatile("ldmatrix.sync.aligned.m8n8.x2.shared.b16 {%0,%1}, [%2];" \
        : "=r"(r0),"=r"(r1) : "r"(addr))
#define MMA16816(c,a,b) \
    asm volatile("mma.sync.aligned.m16n8k16.row.col.f32.bf16.bf16.f32 " \
        "{%0,%1,%2,%3}, {%4,%5,%6,%7}, {%8,%9}, {%0,%1,%2,%3};" \
        : "+f"((c)[0]),"+f"((c)[1]),"+f"((c)[2]),"+f"((c)[3]) \
        : "r"((a)[0]),"r"((a)[1]),"r"((a)[2]),"r"((a)[3]), "r"((b)[0]),"r"((b)[1]))

// ---------------------------------------------------------------------------
// k0: split w2 into bf16 hi/lo (vectorized). 196 x 256 covers 200704/4.
// ---------------------------------------------------------------------------
__global__ void __launch_bounds__(256) k0_w2split(const float* __restrict__ w2) {
    int i = blockIdx.x * 256 + threadIdx.x;
    float4 v = ((const float4*)w2)[i];
    __nv_bfloat16 h0 = __float2bfloat16(v.x), h1 = __float2bfloat16(v.y);
    __nv_bfloat16 h2 = __float2bfloat16(v.z), h3 = __float2bfloat16(v.w);
    ushort4 hh, ll;
    hh.x = __bfloat16_as_ushort(h0); hh.y = __bfloat16_as_ushort(h1);
    hh.z = __bfloat16_as_ushort(h2); hh.w = __bfloat16_as_ushort(h3);
    ll.x = __bfloat16_as_ushort(__float2bfloat16(v.x - __bfloat162float(h0)));
    ll.y = __bfloat16_as_ushort(__float2bfloat16(v.y - __bfloat162float(h1)));
    ll.z = __bfloat16_as_ushort(__float2bfloat16(v.z - __bfloat162float(h2)));
    ll.w = __bfloat16_as_ushort(__float2bfloat16(v.w - __bfloat162float(h3)));
    ((ushort4*)g_w2hi)[i] = hh;
    ((ushort4*)g_w2lo)[i] = ll;
}

// ---------------------------------------------------------------------------
// k1: y = relu(bn(conv1(x))), bf16 hi/lo at [b][hw][cr]
// ---------------------------------------------------------------------------
__global__ void __launch_bounds__(256) k1_conv_bn_relu(
    const float* __restrict__ x,  const float* __restrict__ w1,
    const float* __restrict__ b1, const float* __restrict__ gamma,
    const float* __restrict__ beta, const float* __restrict__ mean,
    const float* __restrict__ var)
{
    __shared__ float w1s[C * 9];
    const int tid = threadIdx.x;
    const int cr0 = blockIdx.y * 8;

    for (int idx = tid; idx < 8 * C; idx += 256) {
        int cr = idx >> 8;
        int c  = idx & 255;
        w1s[c * 9 + cr] = w1[(cr0 + cr) * C + c];
    }
    __syncthreads();

    const int p  = blockIdx.x * 256 + tid;
    const int b  = p / HW;
    const int hw = p - b * HW;
    const float* xb = x + (size_t)b * C * HW + hw;

    float acc[8];
#pragma unroll
    for (int i = 0; i < 8; i++) acc[i] = 0.f;

#pragma unroll 4
    for (int c = 0; c < C; c++) {
        float xv = xb[c * HW];
#pragma unroll
        for (int i = 0; i < 8; i++) acc[i] += w1s[c * 9 + i] * xv;
    }

#pragma unroll
    for (int i = 0; i < 8; i++) {
        int cr = cr0 + i;
        float inv   = gamma[cr] * rsqrtf(var[cr] + 1e-5f);
        float shift = beta[cr] - mean[cr] * inv;
        float v = fmaxf((acc[i] + b1[cr]) * inv + shift, 0.f);
        __nv_bfloat16 h = __float2bfloat16(v);
        size_t o = (size_t)(b * HW + hw) * Cr + cr;
        g_yhi[o] = h;
        g_ylo[o] = __float2bfloat16(v - __bfloat162float(h));
    }
}

// ---------------------------------------------------------------------------
// k2: block = (row strip th, batch, group). grid (7, 4, 64), 256 threads.
//   A (w2 hi/lo) staged + ldmatrix'd to REGISTERS once; x halo staged once;
//   then 7 chunks (8x8 px): stage B, MMA (merged 3-pass), epilogue, involution.
//   Warp grid: mh (2) x nq (4); per warp 2 m-tiles x 2 n-tiles.
// smem (dynamic 66048B):
//   Ahi@0 Alo@9216 Bhi@18432 Blo@27648  (rows stride 144B)
//   wts@36864 [49][65]f32   xs@49664 [4][14][72]f32   b2s@65792 [49]f32
// ---------------------------------------------------------------------------
#define S_AHI 0u
#define S_ALO 9216u
#define S_BHI 18432u
#define S_BLO 27648u
#define S_WTS 36864u
#define S_XS  49664u
#define S_B2  65792u
#define SMEM_K2 66048

__global__ void __launch_bounds__(256, 2) k2_involution(
    const float* __restrict__ x, const float* __restrict__ b2,
    float* __restrict__ out)
{
    extern __shared__ __align__(16) char buf[];
    const uint32_t sb = smem_u32(buf);
    const int tid = threadIdx.x, wid = tid >> 5, lane = tid & 31;
    const int mh = wid & 1, nq = wid >> 1;
    const int b  = blockIdx.y;
    const int g  = blockIdx.z;
    const int th = blockIdx.x;
    const int h0 = th * 8;

    float* wts = (float*)(buf + S_WTS);
    float* xs  = (float*)(buf + S_XS);
    float* b2s = (float*)(buf + S_B2);

    // ---- stage A (w2 hi/lo): 49 rows x 8 uint4, stride 144B ----
    const uint4* w2hi4 = (const uint4*)g_w2hi;
    const uint4* w2lo4 = (const uint4*)g_w2lo;
    for (int idx = tid; idx < K2 * 8; idx += 256) {
        int r = idx >> 3, j = idx & 7;
        int gidx = (g * K2 + r) * 8 + j;
        uint32_t off = (uint32_t)(r * 144 + j * 16);
        *(uint4*)(buf + S_AHI + off) = w2hi4[gidx];
        *(uint4*)(buf + S_ALO + off) = w2lo4[gidx];
    }
    if (tid < K2) b2s[tid] = b2[g * K2 + tid];
    // ---- stage x halo strip: 4 ch x 14 rows x 62 cols (pitch 72) ----
    for (int idx = tid; idx < 4 * 14 * 62; idx += 256) {
        int ch = idx / 868, rem = idx - ch * 868;
        int r = rem / 62, col = rem - r * 62;
        int hh = h0 + r - 3, ww = col - 3;
        float v = 0.f;
        if (hh >= 0 && hh < Hdim && ww >= 0 && ww < Hdim)
            v = x[((size_t)(b * C + g * 4 + ch) * Hdim + hh) * Hdim + ww];
        xs[(ch * 14 + r) * 72 + col] = v;
    }
    __syncthreads();

    // ---- ldmatrix A fragments into registers (persist across chunks) ----
    uint32_t ah[2][4][4], al[2][4][4];
    const uint32_t aoff = ((uint32_t)(lane & 15) * 72 + (uint32_t)(lane >> 4) * 8) * 2;
#pragma unroll
    for (int mt = 0; mt < 2; mt++) {
        uint32_t rowb = (uint32_t)((mh * 2 + mt) * 16 * 144);
#pragma unroll
        for (int kk = 0; kk < 4; kk++) {
            LDSM_X4(ah[mt][kk][0], ah[mt][kk][1], ah[mt][kk][2], ah[mt][kk][3],
                    sb + S_AHI + aoff + rowb + (uint32_t)(kk * 32));
            LDSM_X4(al[mt][kk][0], al[mt][kk][1], al[mt][kk][2], al[mt][kk][3],
                    sb + S_ALO + aoff + rowb + (uint32_t)(kk * 32));
        }
    }

    const uint32_t boff = ((uint32_t)(nq * 16 + (lane & 7)) * 72
                         + (uint32_t)((lane >> 3) & 1) * 8) * 2;

    const uint4* yhi4 = (const uint4*)g_yhi;
    const uint4* ylo4 = (const uint4*)g_ylo;

    const int pixi = tid & 63;
    const int ch   = tid >> 6;
    const int phi  = pixi >> 3, pwi = pixi & 7;
    const float* xsrow = xs + (ch * 14 + phi) * 72 + pwi;   // + w0 + ky*72 + kx

    for (int tw = 0; tw < 7; tw++) {
        const int w0 = tw * 8;

        // ---- stage B chunk (64 px x 8 uint4, hi+lo) ----
        for (int idx = tid; idx < 512; idx += 256) {
            int n = idx >> 3, j = idx & 7;
            int hw = (h0 + (n >> 3)) * Hdim + w0 + (n & 7);
            int gidx = (b * HW + hw) * 8 + j;
            uint32_t off = (uint32_t)(n * 144 + j * 16);
            *(uint4*)(buf + S_BHI + off) = yhi4[gidx];
            *(uint4*)(buf + S_BLO + off) = ylo4[gidx];
        }
        __syncthreads();

        // ---- GEMM: merged 3-pass, A in registers ----
        float c[2][2][4];
#pragma unroll
        for (int mt = 0; mt < 2; mt++)
#pragma unroll
            for (int nt = 0; nt < 2; nt++)
#pragma unroll
                for (int i = 0; i < 4; i++) c[mt][nt][i] = 0.f;

#pragma unroll
        for (int kk = 0; kk < 4; kk++) {
            uint32_t bh[2][2], bl[2][2];
#pragma unroll
            for (int nt = 0; nt < 2; nt++) {
                uint32_t o = boff + (uint32_t)(nt * 8 * 144 + kk * 32);
                LDSM_X2(bh[nt][0], bh[nt][1], sb + S_BHI + o);
                LDSM_X2(bl[nt][0], bl[nt][1], sb + S_BLO + o);
            }
#pragma unroll
            for (int mt = 0; mt < 2; mt++)
#pragma unroll
                for (int nt = 0; nt < 2; nt++) {
                    MMA16816(c[mt][nt], ah[mt][kk], bh[nt]);
                    MMA16816(c[mt][nt], ah[mt][kk], bl[nt]);
                    MMA16816(c[mt][nt], al[mt][kk], bh[nt]);
                }
        }
        __syncthreads();   // B consumed; prev involution done (via s1 ordering)

        // ---- epilogue: fragments -> wts (+bias) ----
#pragma unroll
        for (int mt = 0; mt < 2; mt++) {
            int r0 = (mh * 2 + mt) * 16 + (lane >> 2);
            int r1 = r0 + 8;
#pragma unroll
            for (int nt = 0; nt < 2; nt++) {
                int col = nq * 16 + nt * 8 + (lane & 3) * 2;
                if (r0 < K2) {
                    float bias = b2s[r0];
                    wts[r0 * 65 + col]     = c[mt][nt][0] + bias;
                    wts[r0 * 65 + col + 1] = c[mt][nt][1] + bias;
                }
                if (r1 < K2) {
                    float bias = b2s[r1];
                    wts[r1 * 65 + col]     = c[mt][nt][2] + bias;
                    wts[r1 * 65 + col + 1] = c[mt][nt][3] + bias;
                }
            }
        }
        __syncthreads();

        // ---- involution: thread = (pixel, channel) ----
        const float* xb = xsrow + w0;
        float s = 0.f;
#pragma unroll
        for (int ky = 0; ky < 7; ky++) {
#pragma unroll
            for (int kx = 0; kx < 7; kx++) {
                s += wts[(ky * 7 + kx) * 65 + pixi] * xb[ky * 72 + kx];
            }
        }
        out[((size_t)(b * C + g * 4 + ch) * Hdim + h0 + phi) * Hdim + w0 + pwi] = s;
    }
}

extern "C" void kernel_launch(void* const* d_in, const int* in_sizes, int n_in,
                              void* d_out, int out_size)
{
    const float* x     = (const float*)d_in[0];
    const float* w1    = (const float*)d_in[1];
    const float* b1    = (const float*)d_in[2];
    const float* gamma = (const float*)d_in[3];
    const float* beta  = (const float*)d_in[4];
    const float* mean  = (const float*)d_in[5];
    const float* var   = (const float*)d_in[6];
    const float* w2    = (const float*)d_in[7];
    const float* b2    = (const float*)d_in[8];
    float* out = (float*)d_out;

    cudaFuncSetAttribute(k2_involution,
                         cudaFuncAttributeMaxDynamicSharedMemorySize, SMEM_K2);

    k0_w2split<<<196, 256>>>(w2);

    dim3 g1(49, 8);
    k1_conv_bn_relu<<<g1, 256>>>(x, w1, b1, gamma, beta, mean, var);

    dim3 g2(7, 4, 64);   // row strips x batch x groups
    k2_involution<<<g2, 256, SMEM_K2>>>(x, b2, out);
}

// round 6
// speedup vs baseline: 3.8194x; 1.1296x over previous
#include <cuda_runtime.h>
#include <cuda_fp16.h>
#include <cstdint>

// ---------------------------------------------------------------------------
// involution_81106162418291 — fp16 2-pass mma.sync + cp.async double-buffer
// B=4, C=256, H=W=56, GC=4 -> G=64, K=7 -> K2=49, Cr=64, stride=1, pad=3
// ---------------------------------------------------------------------------

#define Bsz 4
#define C    256
#define Cr   64
#define HW   3136
#define Hdim 56
#define G    64
#define K2   49

__device__ __half g_yh[Bsz * HW * Cr];     // y hi, [b][hw][cr]
__device__ __half g_yl[Bsz * HW * Cr];     // y lo
__device__ __half g_w2h[K2 * G * Cr];      // w2 hi, [row][cr]

__device__ __forceinline__ uint32_t smem_u32(const void* p) {
    uint32_t a;
    asm("{ .reg .u64 t; cvta.to.shared.u64 t, %1; cvt.u32.u64 %0, t; }"
        : "=r"(a) : "l"(p));
    return a;
}

#define LDSM_X4(r0,r1,r2,r3,addr) \
    asm volatile("ldmatrix.sync.aligned.m8n8.x4.shared.b16 {%0,%1,%2,%3}, [%4];" \
        : "=r"(r0),"=r"(r1),"=r"(r2),"=r"(r3) : "r"(addr))
#define LDSM_X2(r0,r1,addr) \
    asm volatile("ldmatrix.sync.aligned.m8n8.x2.shared.b16 {%0,%1}, [%2];" \
        : "=r"(r0),"=r"(r1) : "r"(addr))
#define MMA16816(c,a,b) \
    asm volatile("mma.sync.aligned.m16n8k16.row.col.f32.f16.f16.f32 " \
        "{%0,%1,%2,%3}, {%4,%5,%6,%7}, {%8,%9}, {%0,%1,%2,%3};" \
        : "+f"((c)[0]),"+f"((c)[1]),"+f"((c)[2]),"+f"((c)[3]) \
        : "r"((a)[0]),"r"((a)[1]),"r"((a)[2]),"r"((a)[3]), "r"((b)[0]),"r"((b)[1]))
#define CP_ASYNC16(dst, src) \
    asm volatile("cp.async.cg.shared.global [%0], [%1], 16;" :: "r"(dst), "l"(src))
#define CP_COMMIT() asm volatile("cp.async.commit_group;")
#define CP_WAIT(n)  asm volatile("cp.async.wait_group %0;" :: "n"(n))

// ---------------------------------------------------------------------------
// k0: w2 -> fp16 hi. grid 196 x 256 covers 200704/4.
// ---------------------------------------------------------------------------
__global__ void __launch_bounds__(256) k0_w2split(const float* __restrict__ w2) {
    int i = blockIdx.x * 256 + threadIdx.x;
    float4 v = ((const float4*)w2)[i];
    ushort4 hh;
    hh.x = __half_as_ushort(__float2half(v.x));
    hh.y = __half_as_ushort(__float2half(v.y));
    hh.z = __half_as_ushort(__float2half(v.z));
    hh.w = __half_as_ushort(__float2half(v.w));
    ((ushort4*)g_w2h)[i] = hh;
}

// ---------------------------------------------------------------------------
// k1: y = relu(bn(conv1(x))), fp16 hi/lo at [b][hw][cr]
// w1 smem layout [cr][c] -> warp-uniform float4 broadcasts
// ---------------------------------------------------------------------------
__global__ void __launch_bounds__(256) k1_conv_bn_relu(
    const float* __restrict__ x,  const float* __restrict__ w1,
    const float* __restrict__ b1, const float* __restrict__ gamma,
    const float* __restrict__ beta, const float* __restrict__ mean,
    const float* __restrict__ var)
{
    __shared__ float w1s[8 * 260];           // [cr][c], row pitch 260
    const int tid = threadIdx.x;
    const int cr0 = blockIdx.y * 8;

    for (int idx = tid; idx < 8 * C; idx += 256) {
        int i = idx >> 8;
        int c = idx & 255;
        w1s[i * 260 + c] = w1[(cr0 + i) * C + c];
    }
    __syncthreads();

    const int p  = blockIdx.x * 256 + tid;
    const int b  = p / HW;
    const int hw = p - b * HW;
    const float* xb = x + (size_t)b * C * HW + hw;

    float acc[8];
#pragma unroll
    for (int i = 0; i < 8; i++) acc[i] = 0.f;

#pragma unroll 2
    for (int c = 0; c < C; c += 4) {
        float xv0 = xb[c * HW];
        float xv1 = xb[(c + 1) * HW];
        float xv2 = xb[(c + 2) * HW];
        float xv3 = xb[(c + 3) * HW];
#pragma unroll
        for (int i = 0; i < 8; i++) {
            float4 w = *(const float4*)&w1s[i * 260 + c];
            acc[i] += w.x * xv0 + w.y * xv1 + w.z * xv2 + w.w * xv3;
        }
    }

#pragma unroll
    for (int i = 0; i < 8; i++) {
        int cr = cr0 + i;
        float inv   = gamma[cr] * rsqrtf(var[cr] + 1e-5f);
        float shift = beta[cr] - mean[cr] * inv;
        float v = fmaxf((acc[i] + b1[cr]) * inv + shift, 0.f);
        __half h = __float2half(v);
        size_t o = (size_t)(b * HW + hw) * Cr + cr;
        g_yh[o] = h;
        g_yl[o] = __float2half(v - __half2float(h));
    }
}

// ---------------------------------------------------------------------------
// k2: block = (row strip, batch, group). grid (7, 4, 64), 256 threads.
//   A (w2 fp16 hi) in registers once; x halo once; per chunk:
//   cp.async-prefetched B (hi+lo, double-buffered), 2-pass MMA, epilogue,
//   7x7 involution.
// smem (dynamic 73216B):
//   A@0 (49 rows x 144B)            7168
//   B@7168: 2 bufs x (hi 9216 + lo 9216) = 36864   -> 44032
//   wts@44032 [49][65]f32 = 12800                  -> 56832
//   xs@56832  [4][14][72]f32 = 16128               -> 72960
//   b2s@72960 [49]f32                               -> 73216
// ---------------------------------------------------------------------------
#define S_A   0u
#define S_B   7168u
#define S_WTS 44032u
#define S_XS  56832u
#define S_B2  72960u
#define SMEM_K2 73216

__global__ void __launch_bounds__(256, 2) k2_involution(
    const float* __restrict__ x, const float* __restrict__ b2,
    float* __restrict__ out)
{
    extern __shared__ __align__(16) char buf[];
    const uint32_t sb = smem_u32(buf);
    const int tid = threadIdx.x, wid = tid >> 5, lane = tid & 31;
    const int mh = wid & 1, nq = wid >> 1;
    const int b  = blockIdx.y;
    const int g  = blockIdx.z;
    const int h0 = blockIdx.x * 8;

    float* wts = (float*)(buf + S_WTS);
    float* xs  = (float*)(buf + S_XS);
    float* b2s = (float*)(buf + S_B2);

    // ---- stage A (w2 hi): 49 rows x 8 uint4, stride 144B ----
    const uint4* w2h4 = (const uint4*)g_w2h;
    for (int idx = tid; idx < K2 * 8; idx += 256) {
        int r = idx >> 3, j = idx & 7;
        *(uint4*)(buf + S_A + (uint32_t)(r * 144 + j * 16)) = w2h4[(g * K2 + r) * 8 + j];
    }
    if (tid < K2) b2s[tid] = b2[g * K2 + tid];
    // ---- stage x halo strip: 4 ch x 14 rows x 62 cols (pitch 72) ----
    for (int idx = tid; idx < 4 * 14 * 62; idx += 256) {
        int ch = idx / 868, rem = idx - ch * 868;
        int r = rem / 62, col = rem - r * 62;
        int hh = h0 + r - 3, ww = col - 3;
        float v = 0.f;
        if (hh >= 0 && hh < Hdim && ww >= 0 && ww < Hdim)
            v = x[((size_t)(b * C + g * 4 + ch) * Hdim + hh) * Hdim + ww];
        xs[(ch * 14 + r) * 72 + col] = v;
    }

    // ---- cp.async B stager: 64 rows x 8 x 16B x (hi,lo) = 1024 ops ----
    const char* yhp = (const char*)g_yh;
    const char* ylp = (const char*)g_yl;
    auto stage_B = [&](int tw, int q) {
#pragma unroll
        for (int it = 0; it < 4; it++) {
            int idx  = it * 256 + tid;
            int half = idx >> 9;
            int rem  = idx & 511;
            int n = rem >> 3, j = rem & 7;
            int hw = (h0 + (n >> 3)) * Hdim + tw * 8 + (n & 7);
            uint32_t dst = sb + S_B + (uint32_t)(q * 18432 + half * 9216 + n * 144 + j * 16);
            const char* src = (half ? ylp : yhp) + (size_t)(b * HW + hw) * 128 + j * 16;
            CP_ASYNC16(dst, src);
        }
    };

    stage_B(0, 0);
    CP_COMMIT();
    __syncthreads();    // A + xs visible

    // ---- ldmatrix A fragments into registers (persist) ----
    uint32_t ah[2][4][4];
    const uint32_t aoff = ((uint32_t)(lane & 15) * 72 + (uint32_t)(lane >> 4) * 8) * 2;
#pragma unroll
    for (int mt = 0; mt < 2; mt++) {
        uint32_t rowb = (uint32_t)((mh * 2 + mt) * 16 * 144);
#pragma unroll
        for (int kk = 0; kk < 4; kk++)
            LDSM_X4(ah[mt][kk][0], ah[mt][kk][1], ah[mt][kk][2], ah[mt][kk][3],
                    sb + S_A + aoff + rowb + (uint32_t)(kk * 32));
    }

    const uint32_t boff = ((uint32_t)(nq * 16 + (lane & 7)) * 72
                         + (uint32_t)((lane >> 3) & 1) * 8) * 2;

    const int pixi = tid & 63;
    const int ch   = tid >> 6;
    const int phi  = pixi >> 3, pwi = pixi & 7;
    const float* xsrow = xs + (ch * 14 + phi) * 72 + pwi;

    for (int tw = 0; tw < 7; tw++) {
        const int q  = tw & 1;
        const int w0 = tw * 8;

        if (tw < 6) {
            stage_B(tw + 1, q ^ 1);
            CP_COMMIT();
            CP_WAIT(1);
        } else {
            CP_WAIT(0);
        }
        __syncthreads();   // B(tw) visible; prev involution done (wts reusable)

        // ---- GEMM: 2-pass (Ah*Bh + Ah*Bl), A in registers ----
        const uint32_t bhi = sb + S_B + (uint32_t)(q * 18432);
        const uint32_t blo = bhi + 9216u;
        float c[2][2][4];
#pragma unroll
        for (int mt = 0; mt < 2; mt++)
#pragma unroll
            for (int nt = 0; nt < 2; nt++)
#pragma unroll
                for (int i = 0; i < 4; i++) c[mt][nt][i] = 0.f;

#pragma unroll
        for (int kk = 0; kk < 4; kk++) {
            uint32_t bh[2][2], bl[2][2];
#pragma unroll
            for (int nt = 0; nt < 2; nt++) {
                uint32_t o = boff + (uint32_t)(nt * 8 * 144 + kk * 32);
                LDSM_X2(bh[nt][0], bh[nt][1], bhi + o);
                LDSM_X2(bl[nt][0], bl[nt][1], blo + o);
            }
#pragma unroll
            for (int mt = 0; mt < 2; mt++)
#pragma unroll
                for (int nt = 0; nt < 2; nt++) {
                    MMA16816(c[mt][nt], ah[mt][kk], bh[nt]);
                    MMA16816(c[mt][nt], ah[mt][kk], bl[nt]);
                }
        }
        __syncthreads();   // GEMM ldsm done; involution(tw-1) done

        // ---- epilogue: fragments -> wts (+bias) ----
#pragma unroll
        for (int mt = 0; mt < 2; mt++) {
            int r0 = (mh * 2 + mt) * 16 + (lane >> 2);
            int r1 = r0 + 8;
#pragma unroll
            for (int nt = 0; nt < 2; nt++) {
                int col = nq * 16 + nt * 8 + (lane & 3) * 2;
                if (r0 < K2) {
                    float bias = b2s[r0];
                    wts[r0 * 65 + col]     = c[mt][nt][0] + bias;
                    wts[r0 * 65 + col + 1] = c[mt][nt][1] + bias;
                }
                if (r1 < K2) {
                    float bias = b2s[r1];
                    wts[r1 * 65 + col]     = c[mt][nt][2] + bias;
                    wts[r1 * 65 + col + 1] = c[mt][nt][3] + bias;
                }
            }
        }
        __syncthreads();

        // ---- involution: thread = (pixel, channel) ----
        const float* xb = xsrow + w0;
        float s = 0.f;
#pragma unroll
        for (int ky = 0; ky < 7; ky++) {
#pragma unroll
            for (int kx = 0; kx < 7; kx++) {
                s += wts[(ky * 7 + kx) * 65 + pixi] * xb[ky * 72 + kx];
            }
        }
        out[((size_t)(b * C + g * 4 + ch) * Hdim + h0 + phi) * Hdim + w0 + pwi] = s;
    }
}

extern "C" void kernel_launch(void* const* d_in, const int* in_sizes, int n_in,
                              void* d_out, int out_size)
{
    const float* x     = (const float*)d_in[0];
    const float* w1    = (const float*)d_in[1];
    const float* b1    = (const float*)d_in[2];
    const float* gamma = (const float*)d_in[3];
    const float* beta  = (const float*)d_in[4];
    const float* mean  = (const float*)d_in[5];
    const float* var   = (const float*)d_in[6];
    const float* w2    = (const float*)d_in[7];
    const float* b2    = (const float*)d_in[8];
    float* out = (float*)d_out;

    cudaFuncSetAttribute(k2_involution,
                         cudaFuncAttributeMaxDynamicSharedMemorySize, SMEM_K2);

    k0_w2split<<<196, 256>>>(w2);

    dim3 g1(49, 8);
    k1_conv_bn_relu<<<g1, 256>>>(x, w1, b1, gamma, beta, mean, var);

    dim3 g2(7, 4, 64);
    k2_involution<<<g2, 256, SMEM_K2>>>(x, b2, out);
}

// round 7
// speedup vs baseline: 4.2491x; 1.1125x over previous
#include <cuda_runtime.h>
#include <cuda_fp16.h>
#include <cstdint>

// ---------------------------------------------------------------------------
// involution_81106162418291 — fp16 2-pass mma.sync, 128-thr CTAs, shared-wts
// B=4, C=256, H=W=56, GC=4 -> G=64, K=7 -> K2=49, Cr=64, stride=1, pad=3
// ---------------------------------------------------------------------------

#define Bsz 4
#define C    256
#define Cr   64
#define HW   3136
#define Hdim 56
#define G    64
#define K2   49

__device__ __half g_yh[Bsz * HW * Cr];     // y hi, [b][hw][cr]
__device__ __half g_yl[Bsz * HW * Cr];     // y lo
__device__ __half g_w2h[K2 * G * Cr];      // w2 hi, [row][cr]

__device__ __forceinline__ uint32_t smem_u32(const void* p) {
    uint32_t a;
    asm("{ .reg .u64 t; cvta.to.shared.u64 t, %1; cvt.u32.u64 %0, t; }"
        : "=r"(a) : "l"(p));
    return a;
}

#define LDSM_X4(r0,r1,r2,r3,addr) \
    asm volatile("ldmatrix.sync.aligned.m8n8.x4.shared.b16 {%0,%1,%2,%3}, [%4];" \
        : "=r"(r0),"=r"(r1),"=r"(r2),"=r"(r3) : "r"(addr))
#define LDSM_X2(r0,r1,addr) \
    asm volatile("ldmatrix.sync.aligned.m8n8.x2.shared.b16 {%0,%1}, [%2];" \
        : "=r"(r0),"=r"(r1) : "r"(addr))
#define MMA16816(c,a,b) \
    asm volatile("mma.sync.aligned.m16n8k16.row.col.f32.f16.f16.f32 " \
        "{%0,%1,%2,%3}, {%4,%5,%6,%7}, {%8,%9}, {%0,%1,%2,%3};" \
        : "+f"((c)[0]),"+f"((c)[1]),"+f"((c)[2]),"+f"((c)[3]) \
        : "r"((a)[0]),"r"((a)[1]),"r"((a)[2]),"r"((a)[3]), "r"((b)[0]),"r"((b)[1]))
#define CP_ASYNC16(dst, src) \
    asm volatile("cp.async.cg.shared.global [%0], [%1], 16;" :: "r"(dst), "l"(src))
#define CP_COMMIT() asm volatile("cp.async.commit_group;")
#define CP_WAIT(n)  asm volatile("cp.async.wait_group %0;" :: "n"(n))

// ---------------------------------------------------------------------------
// k0: w2 -> fp16 hi. grid 196 x 256 covers 200704/4.
// ---------------------------------------------------------------------------
__global__ void __launch_bounds__(256) k0_w2split(const float* __restrict__ w2) {
    int i = blockIdx.x * 256 + threadIdx.x;
    float4 v = ((const float4*)w2)[i];
    ushort4 hh;
    hh.x = __half_as_ushort(__float2half(v.x));
    hh.y = __half_as_ushort(__float2half(v.y));
    hh.z = __half_as_ushort(__float2half(v.z));
    hh.w = __half_as_ushort(__float2half(v.w));
    ((ushort4*)g_w2h)[i] = hh;
}

// ---------------------------------------------------------------------------
// k1: y = relu(bn(conv1(x))), fp16 hi/lo at [b][hw][cr]
// grid (49, 4): 16 cr per block; w1 smem [cr][c] warp-uniform float4 reads
// ---------------------------------------------------------------------------
__global__ void __launch_bounds__(256) k1_conv_bn_relu(
    const float* __restrict__ x,  const float* __restrict__ w1,
    const float* __restrict__ b1, const float* __restrict__ gamma,
    const float* __restrict__ beta, const float* __restrict__ mean,
    const float* __restrict__ var)
{
    __shared__ float w1s[16 * 260];          // [cr][c], row pitch 260
    const int tid = threadIdx.x;
    const int cr0 = blockIdx.y * 16;

    for (int idx = tid; idx < 16 * C; idx += 256) {
        int i = idx >> 8;
        int c = idx & 255;
        w1s[i * 260 + c] = w1[(cr0 + i) * C + c];
    }
    __syncthreads();

    const int p  = blockIdx.x * 256 + tid;
    const int b  = p / HW;
    const int hw = p - b * HW;
    const float* xb = x + (size_t)b * C * HW + hw;

    float acc[16];
#pragma unroll
    for (int i = 0; i < 16; i++) acc[i] = 0.f;

    for (int c = 0; c < C; c += 4) {
        float xv0 = xb[c * HW];
        float xv1 = xb[(c + 1) * HW];
        float xv2 = xb[(c + 2) * HW];
        float xv3 = xb[(c + 3) * HW];
#pragma unroll
        for (int i = 0; i < 16; i++) {
            float4 w = *(const float4*)&w1s[i * 260 + c];
            acc[i] += w.x * xv0 + w.y * xv1 + w.z * xv2 + w.w * xv3;
        }
    }

#pragma unroll
    for (int i = 0; i < 16; i++) {
        int cr = cr0 + i;
        float inv   = gamma[cr] * rsqrtf(var[cr] + 1e-5f);
        float shift = beta[cr] - mean[cr] * inv;
        float v = fmaxf((acc[i] + b1[cr]) * inv + shift, 0.f);
        __half h = __float2half(v);
        size_t o = (size_t)(b * HW + hw) * Cr + cr;
        g_yh[o] = h;
        g_yl[o] = __float2half(v - __half2float(h));
    }
}

// ---------------------------------------------------------------------------
// k2: block = (row strip, batch, group). grid (7, 4, 64), 128 threads, 3/SM.
//   A (w2 fp16 hi) in regs once (4 m-tiles/warp); x halo once; per chunk:
//   cp.async double-buffered B (hi+lo), 2-pass MMA (64/warp), epilogue,
//   involution with thread=(px, ch-pair) sharing wts loads across 2 channels.
// smem (dynamic 73216B): A@0 7168 | B@7168 2x(9216+9216) | wts@44032 12800 |
//                        xs@56832 16128 | b2s@72960 196
// ---------------------------------------------------------------------------
#define S_A   0u
#define S_B   7168u
#define S_WTS 44032u
#define S_XS  56832u
#define S_B2  72960u
#define SMEM_K2 73216

__global__ void __launch_bounds__(128, 3) k2_involution(
    const float* __restrict__ x, const float* __restrict__ b2,
    float* __restrict__ out)
{
    extern __shared__ __align__(16) char buf[];
    const uint32_t sb = smem_u32(buf);
    const int tid = threadIdx.x, wid = tid >> 5, lane = tid & 31;
    const int nq = wid;                  // warp owns px [16nq, 16nq+16)
    const int b  = blockIdx.y;
    const int g  = blockIdx.z;
    const int h0 = blockIdx.x * 8;

    float* wts = (float*)(buf + S_WTS);
    float* xs  = (float*)(buf + S_XS);
    float* b2s = (float*)(buf + S_B2);

    // ---- stage A (w2 hi): 49 rows x 8 uint4, stride 144B ----
    const uint4* w2h4 = (const uint4*)g_w2h;
    for (int idx = tid; idx < K2 * 8; idx += 128) {
        int r = idx >> 3, j = idx & 7;
        *(uint4*)(buf + S_A + (uint32_t)(r * 144 + j * 16)) = w2h4[(g * K2 + r) * 8 + j];
    }
    if (tid < K2) b2s[tid] = b2[g * K2 + tid];
    // ---- stage x halo strip: 4 ch x 14 rows x 62 cols (pitch 72) ----
    for (int idx = tid; idx < 4 * 14 * 62; idx += 128) {
        int ch = idx / 868, rem = idx - ch * 868;
        int r = rem / 62, col = rem - r * 62;
        int hh = h0 + r - 3, ww = col - 3;
        float v = 0.f;
        if (hh >= 0 && hh < Hdim && ww >= 0 && ww < Hdim)
            v = x[((size_t)(b * C + g * 4 + ch) * Hdim + hh) * Hdim + ww];
        xs[(ch * 14 + r) * 72 + col] = v;
    }

    // ---- cp.async B stager: 64 rows x 8 x 16B x (hi,lo) = 1024 ops ----
    const char* yhp = (const char*)g_yh;
    const char* ylp = (const char*)g_yl;
    auto stage_B = [&](int tw, int q) {
#pragma unroll
        for (int it = 0; it < 8; it++) {
            int idx  = it * 128 + tid;
            int half = idx >> 9;
            int rem  = idx & 511;
            int n = rem >> 3, j = rem & 7;
            int hw = (h0 + (n >> 3)) * Hdim + tw * 8 + (n & 7);
            uint32_t dst = sb + S_B + (uint32_t)(q * 18432 + half * 9216 + n * 144 + j * 16);
            const char* src = (half ? ylp : yhp) + (size_t)(b * HW + hw) * 128 + j * 16;
            CP_ASYNC16(dst, src);
        }
    };

    stage_B(0, 0);
    CP_COMMIT();
    __syncthreads();    // A + xs visible

    // ---- ldmatrix A fragments into registers (4 m-tiles, persist) ----
    uint32_t ah[4][4][4];
    const uint32_t aoff = ((uint32_t)(lane & 15) * 72 + (uint32_t)(lane >> 4) * 8) * 2;
#pragma unroll
    for (int mt = 0; mt < 4; mt++) {
        uint32_t rowb = (uint32_t)(mt * 16 * 144);
#pragma unroll
        for (int kk = 0; kk < 4; kk++)
            LDSM_X4(ah[mt][kk][0], ah[mt][kk][1], ah[mt][kk][2], ah[mt][kk][3],
                    sb + S_A + aoff + rowb + (uint32_t)(kk * 32));
    }

    const uint32_t boff = ((uint32_t)(nq * 16 + (lane & 7)) * 72
                         + (uint32_t)((lane >> 3) & 1) * 8) * 2;

    // involution mapping: thread = (pixel, ch-pair)
    const int pixi = tid & 63;
    const int cp   = tid >> 6;                 // 0..1 -> channels cp, cp+2
    const int phi  = pixi >> 3, pwi = pixi & 7;
    const float* xr0 = xs + ((cp)     * 14 + phi) * 72 + pwi;
    const float* xr1 = xs + ((cp + 2) * 14 + phi) * 72 + pwi;

    for (int tw = 0; tw < 7; tw++) {
        const int q  = tw & 1;
        const int w0 = tw * 8;

        if (tw < 6) {
            stage_B(tw + 1, q ^ 1);
            CP_COMMIT();
            CP_WAIT(1);
        } else {
            CP_WAIT(0);
        }
        __syncthreads();   // B(tw) visible; prev involution done (wts reusable)

        // ---- GEMM: 2-pass (Ah*Bh + Ah*Bl), A in registers ----
        const uint32_t bhi = sb + S_B + (uint32_t)(q * 18432);
        const uint32_t blo = bhi + 9216u;
        float c[4][2][4];
#pragma unroll
        for (int mt = 0; mt < 4; mt++)
#pragma unroll
            for (int nt = 0; nt < 2; nt++)
#pragma unroll
                for (int i = 0; i < 4; i++) c[mt][nt][i] = 0.f;

#pragma unroll
        for (int kk = 0; kk < 4; kk++) {
            uint32_t bh[2][2], bl[2][2];
#pragma unroll
            for (int nt = 0; nt < 2; nt++) {
                uint32_t o = boff + (uint32_t)(nt * 8 * 144 + kk * 32);
                LDSM_X2(bh[nt][0], bh[nt][1], bhi + o);
                LDSM_X2(bl[nt][0], bl[nt][1], blo + o);
            }
#pragma unroll
            for (int mt = 0; mt < 4; mt++)
#pragma unroll
                for (int nt = 0; nt < 2; nt++) {
                    MMA16816(c[mt][nt], ah[mt][kk], bh[nt]);
                    MMA16816(c[mt][nt], ah[mt][kk], bl[nt]);
                }
        }
        __syncthreads();   // GEMM ldsm done; involution(tw-1) done

        // ---- epilogue: fragments -> wts (+bias) ----
#pragma unroll
        for (int mt = 0; mt < 4; mt++) {
            int r0 = mt * 16 + (lane >> 2);
            int r1 = r0 + 8;
#pragma unroll
            for (int nt = 0; nt < 2; nt++) {
                int col = nq * 16 + nt * 8 + (lane & 3) * 2;
                if (r0 < K2) {
                    float bias = b2s[r0];
                    wts[r0 * 65 + col]     = c[mt][nt][0] + bias;
                    wts[r0 * 65 + col + 1] = c[mt][nt][1] + bias;
                }
                if (r1 < K2) {
                    float bias = b2s[r1];
                    wts[r1 * 65 + col]     = c[mt][nt][2] + bias;
                    wts[r1 * 65 + col + 1] = c[mt][nt][3] + bias;
                }
            }
        }
        __syncthreads();

        // ---- involution: one wts load feeds 2 channels ----
        const float* xb0 = xr0 + w0;
        const float* xb1 = xr1 + w0;
        float s0 = 0.f, s1 = 0.f;
#pragma unroll
        for (int ky = 0; ky < 7; ky++) {
#pragma unroll
            for (int kx = 0; kx < 7; kx++) {
                float wk = wts[(ky * 7 + kx) * 65 + pixi];
                s0 += wk * xb0[ky * 72 + kx];
                s1 += wk * xb1[ky * 72 + kx];
            }
        }
        size_t o0 = ((size_t)(b * C + g * 4 + cp)     * Hdim + h0 + phi) * Hdim + w0 + pwi;
        size_t o1 = ((size_t)(b * C + g * 4 + cp + 2) * Hdim + h0 + phi) * Hdim + w0 + pwi;
        out[o0] = s0;
        out[o1] = s1;
    }
}

extern "C" void kernel_launch(void* const* d_in, const int* in_sizes, int n_in,
                              void* d_out, int out_size)
{
    const float* x     = (const float*)d_in[0];
    const float* w1    = (const float*)d_in[1];
    const float* b1    = (const float*)d_in[2];
    const float* gamma = (const float*)d_in[3];
    const float* beta  = (const float*)d_in[4];
    const float* mean  = (const float*)d_in[5];
    const float* var   = (const float*)d_in[6];
    const float* w2    = (const float*)d_in[7];
    const float* b2    = (const float*)d_in[8];
    float* out = (float*)d_out;

    cudaFuncSetAttribute(k2_involution,
                         cudaFuncAttributeMaxDynamicSharedMemorySize, SMEM_K2);

    k0_w2split<<<196, 256>>>(w2);

    dim3 g1(49, 4);
    k1_conv_bn_relu<<<g1, 256>>>(x, w1, b1, gamma, beta, mean, var);

    dim3 g2(7, 4, 64);
    k2_involution<<<g2, 128, SMEM_K2>>>(x, b2, out);
}